// round 16
// baseline (speedup 1.0000x reference)
#include <cuda_runtime.h>
#include <cuda_bf16.h>
#include <cstdint>

#define NN 50000
#define EE 800000
#define HIDC 128
#define OUTC 64
#define EPSF 1e-5f
#define NCHUNK 196   // ceil(NN/256)

// ---------------- scratch (device globals) ----------------
__device__ float g_deg[NN];
__device__ float g_dinv[NN];
__device__ float g_h[(size_t)NN * HIDC];
__device__ float g_sum[HIDC];
__device__ float g_sumsq[HIDC];
// split-bf16 activation operands
__device__ __nv_bfloat16 g_xhi[(size_t)NN * HIDC];
__device__ __nv_bfloat16 g_xlo[(size_t)NN * HIDC];
__device__ __nv_bfloat16 g_t1hi[(size_t)NN * HIDC];
__device__ __nv_bfloat16 g_t1lo[(size_t)NN * HIDC];
__device__ __nv_bfloat16 g_hhi[(size_t)NN * HIDC];
__device__ __nv_bfloat16 g_hlo[(size_t)NN * HIDC];
__device__ __nv_bfloat16 g_thhi[(size_t)NN * HIDC];
__device__ __nv_bfloat16 g_thlo[(size_t)NN * HIDC];
// CSR scratch
__device__ int   g_cnt[NN];
__device__ unsigned long long g_scanstate[NCHUNK];
__device__ int   g_rowptr[NN + 1];
__device__ int   g_cursor[NN];
__device__ int   g_csr_src[EE];
// split-bf16 weights, pre-transposed: [N=128][K=256]
__device__ __nv_bfloat16 g_w1hi[128 * 256];
__device__ __nv_bfloat16 g_w1lo[128 * 256];
__device__ __nv_bfloat16 g_w2hi[128 * 256];
__device__ __nv_bfloat16 g_w2lo[128 * 256];
__device__ float g_bias2[128];

// ---------------- helpers ----------------
__device__ __forceinline__ uint32_t smem_u32(const void* p) {
    uint32_t a;
    asm("{ .reg .u64 t; cvta.to.shared.u64 t, %1; cvt.u32.u64 %0, t; }" : "=r"(a) : "l"(p));
    return a;
}
__device__ __forceinline__ void ldsm4(uint32_t* r, uint32_t addr) {
    asm volatile("ldmatrix.sync.aligned.m8n8.x4.shared.b16 {%0,%1,%2,%3}, [%4];"
                 : "=r"(r[0]), "=r"(r[1]), "=r"(r[2]), "=r"(r[3]) : "r"(addr));
}
__device__ __forceinline__ void mma_bf16(float* c, const uint32_t* a, const uint32_t* b) {
    asm volatile("mma.sync.aligned.m16n8k16.row.col.f32.bf16.bf16.f32 "
                 "{%0,%1,%2,%3}, {%4,%5,%6,%7}, {%8,%9}, {%0,%1,%2,%3};"
                 : "+f"(c[0]), "+f"(c[1]), "+f"(c[2]), "+f"(c[3])
                 : "r"(a[0]), "r"(a[1]), "r"(a[2]), "r"(a[3]), "r"(b[0]), "r"(b[1]));
}
__device__ __forceinline__ void cpa16(uint32_t smem, const void* gmem, int size) {
    asm volatile("cp.async.cg.shared.global [%0], [%1], 16, %2;"
                 :: "r"(smem), "l"(gmem), "r"(size) : "memory");
}
#define CP_COMMIT() asm volatile("cp.async.commit_group;" ::: "memory")
#define CP_WAIT0()  asm volatile("cp.async.wait_group 0;" ::: "memory")
#define CP_WAIT1()  asm volatile("cp.async.wait_group 1;" ::: "memory")

__device__ __forceinline__ void split_store4(float4 v, __nv_bfloat16* hip, __nv_bfloat16* lop) {
    __nv_bfloat162 h01, h23, l01, l23;
    h01.x = __float2bfloat16(v.x); h01.y = __float2bfloat16(v.y);
    h23.x = __float2bfloat16(v.z); h23.y = __float2bfloat16(v.w);
    l01.x = __float2bfloat16(v.x - __bfloat162float(h01.x));
    l01.y = __float2bfloat16(v.y - __bfloat162float(h01.y));
    l23.x = __float2bfloat16(v.z - __bfloat162float(h23.x));
    l23.y = __float2bfloat16(v.w - __bfloat162float(h23.y));
    *(__nv_bfloat162*)(hip) = h01;
    *(__nv_bfloat162*)(hip + 2) = h23;
    *(__nv_bfloat162*)(lop) = l01;
    *(__nv_bfloat162*)(lop + 2) = l23;
}

// ---------------- prep: histograms (1 edge/thread) + weight split + reset ----------------
__global__ void k_prep(const int* __restrict__ src, const int* __restrict__ dst,
                       const float* __restrict__ W1_0, const float* __restrict__ W1_1,
                       const float* __restrict__ Wmu0, const float* __restrict__ Wmu1,
                       const float* __restrict__ Wls0, const float* __restrict__ Wls1,
                       const float* __restrict__ bmu, const float* __restrict__ bls) {
    int e = blockIdx.x * blockDim.x + threadIdx.x;
    if (blockIdx.x == 0) {
        if (threadIdx.x < 128) {
            g_sum[threadIdx.x] = 0.f;
            g_sumsq[threadIdx.x] = 0.f;
            g_bias2[threadIdx.x] = (threadIdx.x < 64) ? bmu[threadIdx.x] : bls[threadIdx.x - 64];
        }
        if (threadIdx.x < NCHUNK) g_scanstate[threadIdx.x] = 0ULL;
    }
    if (e < 65536) {
        int stage = e >> 15;
        int r = e & 32767;
        int j = r >> 8, k = r & 255;
        float w;
        if (stage == 0) {
            w = (k < 128) ? W1_0[k * HIDC + j] : W1_1[(k - 128) * HIDC + j];
        } else {
            if (j < 64) w = (k < 128) ? Wmu0[k * OUTC + j] : Wmu1[(k - 128) * OUTC + j];
            else        w = (k < 128) ? Wls0[k * OUTC + (j - 64)] : Wls1[(k - 128) * OUTC + (j - 64)];
        }
        __nv_bfloat16 hi = __float2bfloat16(w);
        __nv_bfloat16 lo = __float2bfloat16(w - __bfloat162float(hi));
        if (stage == 0) { g_w1hi[r] = hi; g_w1lo[r] = lo; }
        else            { g_w2hi[r] = hi; g_w2lo[r] = lo; }
    }
    if (e < EE) {
        atomicAdd(&g_deg[src[e]], 1.0f);
        atomicAdd(&g_cnt[dst[e]], 1);
    }
}

// ---------------- single-kernel decoupled-lookback scan + dinv + self-clean ----------------
__global__ void __launch_bounds__(256) k_scan() {
    __shared__ int s[256];
    __shared__ int s_prefix;
    int b = blockIdx.x;
    int t = threadIdx.x;
    int c = b * 256 + t;
    int v = 0;
    if (c < NN) {
        v = g_cnt[c];
        float d = g_deg[c];
        g_dinv[c] = (d > 0.5f) ? rsqrtf(d) : 0.f;
        g_deg[c] = 0.f;
        g_cnt[c] = 0;
    }
    s[t] = v;
    __syncthreads();
    for (int off = 1; off < 256; off <<= 1) {
        int u = (t >= off) ? s[t - off] : 0;
        __syncthreads();
        s[t] += u;
        __syncthreads();
    }
    int incl = s[t];
    int total = s[255];
    if (t == 0) {
        if (b == 0) {
            atomicExch(&g_scanstate[0], (2ULL << 32) | (unsigned long long)(unsigned)total);
            s_prefix = 0;
        } else {
            atomicExch(&g_scanstate[b], (1ULL << 32) | (unsigned long long)(unsigned)total);
            int prefix = 0;
            int i = b - 1;
            while (true) {
                unsigned long long st;
                do { st = atomicAdd(&g_scanstate[i], 0ULL); } while ((st >> 32) == 0ULL);
                prefix += (int)(st & 0xffffffffULL);
                if ((st >> 32) == 2ULL) break;
                i--;
            }
            atomicExch(&g_scanstate[b], (2ULL << 32) | (unsigned long long)(unsigned)(prefix + total));
            s_prefix = prefix;
        }
    }
    __syncthreads();
    int excl = s_prefix + incl - v;
    if (c < NN) {
        g_rowptr[c] = excl;
        g_cursor[c] = excl;
    }
    if (b == NCHUNK - 1 && t == 255) g_rowptr[NN] = EE;
}

// ---------------- fill (1 edge/thread) ----------------
__global__ void k_fill(const int* __restrict__ src, const int* __restrict__ dst) {
    int e = blockIdx.x * blockDim.x + threadIdx.x;
    if (e < EE) {
        int s = src[e], d = dst[e];
        int p = atomicAdd(&g_cursor[d], 1);
        g_csr_src[p] = s;
    }
}

// ---------------- gather 1: tx1 -> split bf16 ; also splits own X row ----------------
__global__ void __launch_bounds__(128, 12) k_gather1(const float* __restrict__ X) {
    int warp = (int)(((size_t)blockIdx.x * blockDim.x + threadIdx.x) >> 5);
    if (warp >= NN) return;
    int lane = threadIdx.x & 31;
    int d = warp;
    int j = g_rowptr[d], end = g_rowptr[d + 1];
    float ndd = -g_dinv[d];
    float4 acc = make_float4(0.f, 0.f, 0.f, 0.f);
    float4 acc2 = make_float4(0.f, 0.f, 0.f, 0.f);
    while (j < end && (j & 3)) {
        int s0 = __ldg(&g_csr_src[j]);
        float w0 = ndd * __ldg(&g_dinv[s0]);
        float4 v0 = ((const float4*)(X + (size_t)s0 * HIDC))[lane];
        acc.x += w0 * v0.x; acc.y += w0 * v0.y; acc.z += w0 * v0.z; acc.w += w0 * v0.w;
        j++;
    }
    for (; j + 8 <= end; j += 8) {
        int4 ia = *(const int4*)&g_csr_src[j];
        int4 ib = *(const int4*)&g_csr_src[j + 4];
        float w0 = ndd * __ldg(&g_dinv[ia.x]), w1 = ndd * __ldg(&g_dinv[ia.y]);
        float w2 = ndd * __ldg(&g_dinv[ia.z]), w3 = ndd * __ldg(&g_dinv[ia.w]);
        float w4 = ndd * __ldg(&g_dinv[ib.x]), w5 = ndd * __ldg(&g_dinv[ib.y]);
        float w6 = ndd * __ldg(&g_dinv[ib.z]), w7 = ndd * __ldg(&g_dinv[ib.w]);
        float4 v0 = ((const float4*)(X + (size_t)ia.x * HIDC))[lane];
        float4 v1 = ((const float4*)(X + (size_t)ia.y * HIDC))[lane];
        float4 v2 = ((const float4*)(X + (size_t)ia.z * HIDC))[lane];
        float4 v3 = ((const float4*)(X + (size_t)ia.w * HIDC))[lane];
        float4 v4 = ((const float4*)(X + (size_t)ib.x * HIDC))[lane];
        float4 v5 = ((const float4*)(X + (size_t)ib.y * HIDC))[lane];
        float4 v6 = ((const float4*)(X + (size_t)ib.z * HIDC))[lane];
        float4 v7 = ((const float4*)(X + (size_t)ib.w * HIDC))[lane];
        acc.x  += w0 * v0.x + w1 * v1.x + w2 * v2.x + w3 * v3.x;
        acc.y  += w0 * v0.y + w1 * v1.y + w2 * v2.y + w3 * v3.y;
        acc.z  += w0 * v0.z + w1 * v1.z + w2 * v2.z + w3 * v3.z;
        acc.w  += w0 * v0.w + w1 * v1.w + w2 * v2.w + w3 * v3.w;
        acc2.x += w4 * v4.x + w5 * v5.x + w6 * v6.x + w7 * v7.x;
        acc2.y += w4 * v4.y + w5 * v5.y + w6 * v6.y + w7 * v7.y;
        acc2.z += w4 * v4.z + w5 * v5.z + w6 * v6.z + w7 * v7.z;
        acc2.w += w4 * v4.w + w5 * v5.w + w6 * v6.w + w7 * v7.w;
    }
    for (; j < end; j++) {
        int s0 = __ldg(&g_csr_src[j]);
        float w0 = ndd * __ldg(&g_dinv[s0]);
        float4 v0 = ((const float4*)(X + (size_t)s0 * HIDC))[lane];
        acc.x += w0 * v0.x; acc.y += w0 * v0.y; acc.z += w0 * v0.z; acc.w += w0 * v0.w;
    }
    acc.x += acc2.x; acc.y += acc2.y; acc.z += acc2.z; acc.w += acc2.w;
    size_t o = (size_t)d * HIDC + lane * 4;
    split_store4(acc, g_t1hi + o, g_t1lo + o);
    float4 xv = ((const float4*)(X + (size_t)d * HIDC))[lane];
    split_store4(xv, g_xhi + o, g_xlo + o);
}

// ---------------- gather 2: th -> split bf16 + own-row BN split ----------------
__global__ void __launch_bounds__(128, 12) k_gather2(const float* __restrict__ gamma,
                                                     const float* __restrict__ beta) {
    __shared__ float s_sc[128], s_sh[128];
    int t = threadIdx.x;
    {
        float mean = g_sum[t] * (1.0f / NN);
        float var = fmaxf(g_sumsq[t] * (1.0f / NN) - mean * mean, 0.f);
        float sc = gamma[t] * rsqrtf(var + EPSF);
        s_sc[t] = sc;
        s_sh[t] = beta[t] - mean * sc;
    }
    __syncthreads();

    int warp = (int)(((size_t)blockIdx.x * blockDim.x + t) >> 5);
    if (warp >= NN) return;
    int lane = t & 31;
    int d = warp;
    int j = g_rowptr[d], end = g_rowptr[d + 1];
    float ndd = -g_dinv[d];
    float4 sc = *(float4*)&s_sc[lane * 4];
    float4 sh = *(float4*)&s_sh[lane * 4];
    float4 acc = make_float4(0.f, 0.f, 0.f, 0.f);
    float4 acc2 = make_float4(0.f, 0.f, 0.f, 0.f);
#define BNR(v) \
    v.x = fmaxf(fmaf(v.x, sc.x, sh.x), 0.f); \
    v.y = fmaxf(fmaf(v.y, sc.y, sh.y), 0.f); \
    v.z = fmaxf(fmaf(v.z, sc.z, sh.z), 0.f); \
    v.w = fmaxf(fmaf(v.w, sc.w, sh.w), 0.f)
    while (j < end && (j & 3)) {
        int s0 = __ldg(&g_csr_src[j]);
        float w0 = ndd * __ldg(&g_dinv[s0]);
        float4 v0 = ((const float4*)(g_h + (size_t)s0 * HIDC))[lane];
        BNR(v0);
        acc.x += w0 * v0.x; acc.y += w0 * v0.y; acc.z += w0 * v0.z; acc.w += w0 * v0.w;
        j++;
    }
    for (; j + 8 <= end; j += 8) {
        int4 ia = *(const int4*)&g_csr_src[j];
        int4 ib = *(const int4*)&g_csr_src[j + 4];
        float w0 = ndd * __ldg(&g_dinv[ia.x]), w1 = ndd * __ldg(&g_dinv[ia.y]);
        float w2 = ndd * __ldg(&g_dinv[ia.z]), w3 = ndd * __ldg(&g_dinv[ia.w]);
        float w4 = ndd * __ldg(&g_dinv[ib.x]), w5 = ndd * __ldg(&g_dinv[ib.y]);
        float w6 = ndd * __ldg(&g_dinv[ib.z]), w7 = ndd * __ldg(&g_dinv[ib.w]);
        float4 v0 = ((const float4*)(g_h + (size_t)ia.x * HIDC))[lane];
        float4 v1 = ((const float4*)(g_h + (size_t)ia.y * HIDC))[lane];
        float4 v2 = ((const float4*)(g_h + (size_t)ia.z * HIDC))[lane];
        float4 v3 = ((const float4*)(g_h + (size_t)ia.w * HIDC))[lane];
        float4 v4 = ((const float4*)(g_h + (size_t)ib.x * HIDC))[lane];
        float4 v5 = ((const float4*)(g_h + (size_t)ib.y * HIDC))[lane];
        float4 v6 = ((const float4*)(g_h + (size_t)ib.z * HIDC))[lane];
        float4 v7 = ((const float4*)(g_h + (size_t)ib.w * HIDC))[lane];
        BNR(v0); BNR(v1); BNR(v2); BNR(v3); BNR(v4); BNR(v5); BNR(v6); BNR(v7);
        acc.x  += w0 * v0.x + w1 * v1.x + w2 * v2.x + w3 * v3.x;
        acc.y  += w0 * v0.y + w1 * v1.y + w2 * v2.y + w3 * v3.y;
        acc.z  += w0 * v0.z + w1 * v1.z + w2 * v2.z + w3 * v3.z;
        acc.w  += w0 * v0.w + w1 * v1.w + w2 * v2.w + w3 * v3.w;
        acc2.x += w4 * v4.x + w5 * v5.x + w6 * v6.x + w7 * v7.x;
        acc2.y += w4 * v4.y + w5 * v5.y + w6 * v6.y + w7 * v7.y;
        acc2.z += w4 * v4.z + w5 * v5.z + w6 * v6.z + w7 * v7.z;
        acc2.w += w4 * v4.w + w5 * v5.w + w6 * v6.w + w7 * v7.w;
    }
    for (; j < end; j++) {
        int s0 = __ldg(&g_csr_src[j]);
        float w0 = ndd * __ldg(&g_dinv[s0]);
        float4 v0 = ((const float4*)(g_h + (size_t)s0 * HIDC))[lane];
        BNR(v0);
        acc.x += w0 * v0.x; acc.y += w0 * v0.y; acc.z += w0 * v0.z; acc.w += w0 * v0.w;
    }
    acc.x += acc2.x; acc.y += acc2.y; acc.z += acc2.z; acc.w += acc2.w;
    size_t o = (size_t)d * HIDC + lane * 4;
    split_store4(acc, g_thhi + o, g_thlo + o);
    float4 hv = ((const float4*)(g_h + (size_t)d * HIDC))[lane];
    BNR(hv);
    split_store4(hv, g_hhi + o, g_hlo + o);
#undef BNR
}

// ---------------- HMMA split-bf16 GEMM, 2-stage pipelined cp.async, 8 K-chunks of 32 ----------------
#define CSTRIDE 80
#define CTILE (128 * CSTRIDE)
#define STG_B (4 * CTILE)
#define SOFF_AHI 0
#define SOFF_ALO CTILE
#define SOFF_BHI (2 * CTILE)
#define SOFF_BLO (3 * CTILE)
#define SMEM_TOT (2 * STG_B)

__global__ void __launch_bounds__(256, 2) k_tgemm(const float* __restrict__ biasExt,
                                                  float* __restrict__ outExt, int stage) {
    extern __shared__ char sm[];
    __shared__ float s_cs[128], s_cq[128];
    uint32_t sb = smem_u32(sm);
    int t = threadIdx.x;
    int row0 = blockIdx.x * 128;

    if (stage == 0 && t < 128) { s_cs[t] = 0.f; s_cq[t] = 0.f; }

    const __nv_bfloat16* A0hi = stage ? g_hhi : g_xhi;
    const __nv_bfloat16* A0lo = stage ? g_hlo : g_xlo;
    const __nv_bfloat16* A1hi = stage ? g_thhi : g_t1hi;
    const __nv_bfloat16* A1lo = stage ? g_thlo : g_t1lo;
    const __nv_bfloat16* Whi = stage ? g_w2hi : g_w1hi;
    const __nv_bfloat16* Wlo = stage ? g_w2lo : g_w1lo;
    const float* bias = stage ? g_bias2 : biasExt;

    int w = t >> 5, lane = t & 31;
    int warp_m = (w >> 1) * 32, warp_n = (w & 1) * 64;
    int gid = lane >> 2, tig = lane & 3;

    int arow = (lane & 7) + ((lane >> 3) & 1) * 8;
    uint32_t akb = (uint32_t)((lane >> 4) * 16);
    uint32_t aoff0 = (uint32_t)(warp_m + arow) * CSTRIDE + akb;
    uint32_t aoff1 = aoff0 + 16 * CSTRIDE;
    int brow = (lane & 7) + ((lane >> 4) & 1) * 8;
    uint32_t bkb = (uint32_t)(((lane >> 3) & 1) * 16);
    uint32_t boff = (uint32_t)(warp_n + brow) * CSTRIDE + bkb;

    float acc[2][8][4];
#pragma unroll
    for (int mt = 0; mt < 2; mt++)
#pragma unroll
        for (int j = 0; j < 8; j++)
#pragma unroll
            for (int q = 0; q < 4; q++) acc[mt][j][q] = 0.f;

    auto load_chunk = [&](int kc, int buf) {
        int colbase = (kc & 3) * 32;
        const __nv_bfloat16* cAhi = ((kc < 4) ? A0hi : A1hi) + colbase;
        const __nv_bfloat16* cAlo = ((kc < 4) ? A0lo : A1lo) + colbase;
        const __nv_bfloat16* cBhi = Whi + kc * 32;
        const __nv_bfloat16* cBlo = Wlo + kc * 32;
        uint32_t sbase = sb + buf * STG_B;
#pragma unroll
        for (int i = t; i < 2048; i += 256) {
            int tile = i >> 9, idx = i & 511;
            int row = idx >> 2, seg = idx & 3;
            uint32_t soff;
            const void* gp;
            int size = 16;
            if (tile == 0) {
                int gr = row0 + row;
                gp = cAhi + (size_t)gr * HIDC + seg * 8;
                soff = SOFF_AHI + row * CSTRIDE + seg * 16;
                if (gr >= NN) size = 0;
            } else if (tile == 1) {
                int gr = row0 + row;
                gp = cAlo + (size_t)gr * HIDC + seg * 8;
                soff = SOFF_ALO + row * CSTRIDE + seg * 16;
                if (gr >= NN) size = 0;
            } else if (tile == 2) {
                gp = cBhi + row * 256 + seg * 8;
                soff = SOFF_BHI + row * CSTRIDE + seg * 16;
            } else {
                gp = cBlo + row * 256 + seg * 8;
                soff = SOFF_BLO + row * CSTRIDE + seg * 16;
            }
            cpa16(sbase + soff, gp, size);
        }
        CP_COMMIT();
    };

    load_chunk(0, 0);
    for (int kc = 0; kc < 8; kc++) {
        int buf = kc & 1;
        if (kc < 7) {
            load_chunk(kc + 1, buf ^ 1);
            CP_WAIT1();
        } else {
            CP_WAIT0();
        }
        __syncthreads();

        uint32_t sbase = sb + buf * STG_B;
#pragma unroll
        for (int ks = 0; ks < 2; ks++) {
            uint32_t k2 = (uint32_t)ks * 32;
            uint32_t ah0[4], ah1[4], al0[4], al1[4];
            ldsm4(ah0, sbase + SOFF_AHI + aoff0 + k2);
            ldsm4(ah1, sbase + SOFF_AHI + aoff1 + k2);
            ldsm4(al0, sbase + SOFF_ALO + aoff0 + k2);
            ldsm4(al1, sbase + SOFF_ALO + aoff1 + k2);
#pragma unroll
            for (int np = 0; np < 4; np++) {
                uint32_t bh[4], bl[4];
                uint32_t bo = boff + (uint32_t)np * 16 * CSTRIDE + k2;
                ldsm4(bh, sbase + SOFF_BHI + bo);
                ldsm4(bl, sbase + SOFF_BLO + bo);
                mma_bf16(acc[0][2 * np],     ah0, bh);
                mma_bf16(acc[0][2 * np + 1], ah0, bh + 2);
                mma_bf16(acc[1][2 * np],     ah1, bh);
                mma_bf16(acc[1][2 * np + 1], ah1, bh + 2);
                mma_bf16(acc[0][2 * np],     al0, bh);
                mma_bf16(acc[0][2 * np + 1], al0, bh + 2);
                mma_bf16(acc[1][2 * np],     al1, bh);
                mma_bf16(acc[1][2 * np + 1], al1, bh + 2);
                mma_bf16(acc[0][2 * np],     ah0, bl);
                mma_bf16(acc[0][2 * np + 1], ah0, bl + 2);
                mma_bf16(acc[1][2 * np],     ah1, bl);
                mma_bf16(acc[1][2 * np + 1], ah1, bl + 2);
            }
        }
        __syncthreads();
    }

#pragma unroll
    for (int j = 0; j < 8; j++) {
        int n = warp_n + j * 8 + tig * 2;
        float b0 = bias[n], b1 = bias[n + 1];
#pragma unroll
        for (int mt = 0; mt < 2; mt++) {
            int r1 = row0 + warp_m + mt * 16 + gid;
            int r2 = r1 + 8;
            float2 v1 = make_float2(acc[mt][j][0] + b0, acc[mt][j][1] + b1);
            float2 v2 = make_float2(acc[mt][j][2] + b0, acc[mt][j][3] + b1);
            if (stage == 0) {
                if (r1 < NN) *(float2*)(g_h + (size_t)r1 * HIDC + n) = v1;
                if (r2 < NN) *(float2*)(g_h + (size_t)r2 * HIDC + n) = v2;
                float sx = (r1 < NN ? v1.x : 0.f) + (r2 < NN ? v2.x : 0.f);
                float sy = (r1 < NN ? v1.y : 0.f) + (r2 < NN ? v2.y : 0.f);
                float qx = (r1 < NN ? v1.x * v1.x : 0.f) + (r2 < NN ? v2.x * v2.x : 0.f);
                float qy = (r1 < NN ? v1.y * v1.y : 0.f) + (r2 < NN ? v2.y * v2.y : 0.f);
#pragma unroll
                for (int off = 4; off <= 16; off <<= 1) {
                    sx += __shfl_xor_sync(0xffffffffu, sx, off);
                    sy += __shfl_xor_sync(0xffffffffu, sy, off);
                    qx += __shfl_xor_sync(0xffffffffu, qx, off);
                    qy += __shfl_xor_sync(0xffffffffu, qy, off);
                }
                if (gid == 0) {
                    atomicAdd(&s_cs[n], sx);
                    atomicAdd(&s_cs[n + 1], sy);
                    atomicAdd(&s_cq[n], qx);
                    atomicAdd(&s_cq[n + 1], qy);
                }
            } else {
                int nl = (n < 64) ? n : (n - 64);
                size_t obase = (n < 64) ? 0 : (size_t)NN * OUTC;
                if (r1 < NN) *(float2*)(outExt + obase + (size_t)r1 * OUTC + nl) = v1;
                if (r2 < NN) *(float2*)(outExt + obase + (size_t)r2 * OUTC + nl) = v2;
            }
        }
    }

    if (stage == 0) {
        __syncthreads();
        if (t < 128) {
            atomicAdd(&g_sum[t], s_cs[t]);
            atomicAdd(&g_sumsq[t], s_cq[t]);
        }
    }
}

// ---------------- launch ----------------
extern "C" void kernel_launch(void* const* d_in, const int* in_sizes, int n_in,
                              void* d_out, int out_size) {
    const float* x     = (const float*)d_in[0];
    const int*   ei    = (const int*)d_in[1];
    const int*   src   = ei;
    const int*   dst   = ei + EE;
    const float* W1_0  = (const float*)d_in[2];
    const float* W1_1  = (const float*)d_in[3];
    const float* b1    = (const float*)d_in[4];
    const float* gamma = (const float*)d_in[5];
    const float* beta  = (const float*)d_in[6];
    const float* Wmu0  = (const float*)d_in[7];
    const float* Wmu1  = (const float*)d_in[8];
    const float* bmu   = (const float*)d_in[9];
    const float* Wls0  = (const float*)d_in[10];
    const float* Wls1  = (const float*)d_in[11];
    const float* bls   = (const float*)d_in[12];
    float* out = (float*)d_out;

    cudaFuncSetAttribute(k_tgemm, cudaFuncAttributeMaxDynamicSharedMemorySize, SMEM_TOT);

    k_prep<<<(EE + 255) / 256, 256>>>(src, dst, W1_0, W1_1, Wmu0, Wmu1, Wls0, Wls1, bmu, bls); // #1
    k_scan<<<NCHUNK, 256>>>();                                                 // #2
    k_fill<<<(EE + 255) / 256, 256>>>(src, dst);                               // #3
    k_gather1<<<(NN * 32 + 127) / 128, 128>>>(x);                              // #4
    k_tgemm<<<(NN + 127) / 128, 256, SMEM_TOT>>>(b1, nullptr, 0);              // #5
    k_gather2<<<(NN * 32 + 127) / 128, 128>>>(gamma, beta);                    // #6
    k_tgemm<<<(NN + 127) / 128, 256, SMEM_TOT>>>(nullptr, out, 1);             // #7
}

// round 17
// speedup vs baseline: 1.0017x; 1.0017x over previous
#include <cuda_runtime.h>
#include <cuda_bf16.h>
#include <cstdint>

#define NN 50000
#define EE 800000
#define HIDC 128
#define OUTC 64
#define EPSF 1e-5f
#define NCHUNK 196   // ceil(NN/256)

// ---------------- scratch (device globals) ----------------
__device__ float g_deg[NN];
__device__ float g_dinv[NN];
__device__ float g_h[(size_t)NN * HIDC];
__device__ float g_sum[HIDC];
__device__ float g_sumsq[HIDC];
// split-bf16 activation operands
__device__ __nv_bfloat16 g_xhi[(size_t)NN * HIDC];
__device__ __nv_bfloat16 g_xlo[(size_t)NN * HIDC];
__device__ __nv_bfloat16 g_t1hi[(size_t)NN * HIDC];
__device__ __nv_bfloat16 g_t1lo[(size_t)NN * HIDC];
__device__ __nv_bfloat16 g_hhi[(size_t)NN * HIDC];
__device__ __nv_bfloat16 g_hlo[(size_t)NN * HIDC];
__device__ __nv_bfloat16 g_thhi[(size_t)NN * HIDC];
__device__ __nv_bfloat16 g_thlo[(size_t)NN * HIDC];
// CSR scratch
__device__ int   g_cnt[NN];
__device__ unsigned long long g_scanstate[NCHUNK];
__device__ int   g_rowptr[NN + 1];
__device__ int   g_cursor[NN];
__device__ int   g_csr_src[EE];
// split-bf16 weights, pre-transposed: [N=128][K=256]
__device__ __nv_bfloat16 g_w1hi[128 * 256];
__device__ __nv_bfloat16 g_w1lo[128 * 256];
__device__ __nv_bfloat16 g_w2hi[128 * 256];
__device__ __nv_bfloat16 g_w2lo[128 * 256];
__device__ float g_bias2[128];

// ---------------- helpers ----------------
__device__ __forceinline__ uint32_t smem_u32(const void* p) {
    uint32_t a;
    asm("{ .reg .u64 t; cvta.to.shared.u64 t, %1; cvt.u32.u64 %0, t; }" : "=r"(a) : "l"(p));
    return a;
}
__device__ __forceinline__ void ldsm4(uint32_t* r, uint32_t addr) {
    asm volatile("ldmatrix.sync.aligned.m8n8.x4.shared.b16 {%0,%1,%2,%3}, [%4];"
                 : "=r"(r[0]), "=r"(r[1]), "=r"(r[2]), "=r"(r[3]) : "r"(addr));
}
__device__ __forceinline__ void mma_bf16(float* c, const uint32_t* a, const uint32_t* b) {
    asm volatile("mma.sync.aligned.m16n8k16.row.col.f32.bf16.bf16.f32 "
                 "{%0,%1,%2,%3}, {%4,%5,%6,%7}, {%8,%9}, {%0,%1,%2,%3};"
                 : "+f"(c[0]), "+f"(c[1]), "+f"(c[2]), "+f"(c[3])
                 : "r"(a[0]), "r"(a[1]), "r"(a[2]), "r"(a[3]), "r"(b[0]), "r"(b[1]));
}
__device__ __forceinline__ void cpa16(uint32_t smem, const void* gmem, int size) {
    asm volatile("cp.async.cg.shared.global [%0], [%1], 16, %2;"
                 :: "r"(smem), "l"(gmem), "r"(size) : "memory");
}
#define CP_COMMIT() asm volatile("cp.async.commit_group;" ::: "memory")
#define CP_WAIT0()  asm volatile("cp.async.wait_group 0;" ::: "memory")
#define CP_WAIT1()  asm volatile("cp.async.wait_group 1;" ::: "memory")

__device__ __forceinline__ void split_store4(float4 v, __nv_bfloat16* hip, __nv_bfloat16* lop) {
    __nv_bfloat162 h01, h23, l01, l23;
    h01.x = __float2bfloat16(v.x); h01.y = __float2bfloat16(v.y);
    h23.x = __float2bfloat16(v.z); h23.y = __float2bfloat16(v.w);
    l01.x = __float2bfloat16(v.x - __bfloat162float(h01.x));
    l01.y = __float2bfloat16(v.y - __bfloat162float(h01.y));
    l23.x = __float2bfloat16(v.z - __bfloat162float(h23.x));
    l23.y = __float2bfloat16(v.w - __bfloat162float(h23.y));
    *(__nv_bfloat162*)(hip) = h01;
    *(__nv_bfloat162*)(hip + 2) = h23;
    *(__nv_bfloat162*)(lop) = l01;
    *(__nv_bfloat162*)(lop + 2) = l23;
}

// ---------------- prep: histograms (1 edge/thread) + weight split + reset ----------------
__global__ void k_prep(const int* __restrict__ src, const int* __restrict__ dst,
                       const float* __restrict__ W1_0, const float* __restrict__ W1_1,
                       const float* __restrict__ Wmu0, const float* __restrict__ Wmu1,
                       const float* __restrict__ Wls0, const float* __restrict__ Wls1,
                       const float* __restrict__ bmu, const float* __restrict__ bls) {
    int e = blockIdx.x * blockDim.x + threadIdx.x;
    if (blockIdx.x == 0) {
        if (threadIdx.x < 128) {
            g_sum[threadIdx.x] = 0.f;
            g_sumsq[threadIdx.x] = 0.f;
            g_bias2[threadIdx.x] = (threadIdx.x < 64) ? bmu[threadIdx.x] : bls[threadIdx.x - 64];
        }
        if (threadIdx.x < NCHUNK) g_scanstate[threadIdx.x] = 0ULL;
    }
    if (e < 65536) {
        int stage = e >> 15;
        int r = e & 32767;
        int j = r >> 8, k = r & 255;
        float w;
        if (stage == 0) {
            w = (k < 128) ? W1_0[k * HIDC + j] : W1_1[(k - 128) * HIDC + j];
        } else {
            if (j < 64) w = (k < 128) ? Wmu0[k * OUTC + j] : Wmu1[(k - 128) * OUTC + j];
            else        w = (k < 128) ? Wls0[k * OUTC + (j - 64)] : Wls1[(k - 128) * OUTC + (j - 64)];
        }
        __nv_bfloat16 hi = __float2bfloat16(w);
        __nv_bfloat16 lo = __float2bfloat16(w - __bfloat162float(hi));
        if (stage == 0) { g_w1hi[r] = hi; g_w1lo[r] = lo; }
        else            { g_w2hi[r] = hi; g_w2lo[r] = lo; }
    }
    if (e < EE) {
        atomicAdd(&g_deg[src[e]], 1.0f);
        atomicAdd(&g_cnt[dst[e]], 1);
    }
}

// ---------------- single-kernel decoupled-lookback scan + dinv + self-clean ----------------
__global__ void __launch_bounds__(256) k_scan() {
    __shared__ int s[256];
    __shared__ int s_prefix;
    int b = blockIdx.x;
    int t = threadIdx.x;
    int c = b * 256 + t;
    int v = 0;
    if (c < NN) {
        v = g_cnt[c];
        float d = g_deg[c];
        g_dinv[c] = (d > 0.5f) ? rsqrtf(d) : 0.f;
        g_deg[c] = 0.f;
        g_cnt[c] = 0;
    }
    s[t] = v;
    __syncthreads();
    for (int off = 1; off < 256; off <<= 1) {
        int u = (t >= off) ? s[t - off] : 0;
        __syncthreads();
        s[t] += u;
        __syncthreads();
    }
    int incl = s[t];
    int total = s[255];
    if (t == 0) {
        if (b == 0) {
            atomicExch(&g_scanstate[0], (2ULL << 32) | (unsigned long long)(unsigned)total);
            s_prefix = 0;
        } else {
            atomicExch(&g_scanstate[b], (1ULL << 32) | (unsigned long long)(unsigned)total);
            int prefix = 0;
            int i = b - 1;
            while (true) {
                unsigned long long st;
                do { st = atomicAdd(&g_scanstate[i], 0ULL); } while ((st >> 32) == 0ULL);
                prefix += (int)(st & 0xffffffffULL);
                if ((st >> 32) == 2ULL) break;
                i--;
            }
            atomicExch(&g_scanstate[b], (2ULL << 32) | (unsigned long long)(unsigned)(prefix + total));
            s_prefix = prefix;
        }
    }
    __syncthreads();
    int excl = s_prefix + incl - v;
    if (c < NN) {
        g_rowptr[c] = excl;
        g_cursor[c] = excl;
    }
    if (b == NCHUNK - 1 && t == 255) g_rowptr[NN] = EE;
}

// ---------------- fill (1 edge/thread) ----------------
__global__ void k_fill(const int* __restrict__ src, const int* __restrict__ dst) {
    int e = blockIdx.x * blockDim.x + threadIdx.x;
    if (e < EE) {
        int s = src[e], d = dst[e];
        int p = atomicAdd(&g_cursor[d], 1);
        g_csr_src[p] = s;
    }
}

// ---------------- gather 1: tx1 -> split bf16 ; also splits own X row ----------------
__global__ void __launch_bounds__(128, 12) k_gather1(const float* __restrict__ X) {
    int warp = (int)(((size_t)blockIdx.x * blockDim.x + threadIdx.x) >> 5);
    if (warp >= NN) return;
    int lane = threadIdx.x & 31;
    int d = warp;
    int j = g_rowptr[d], end = g_rowptr[d + 1];
    float ndd = -g_dinv[d];
    float4 acc = make_float4(0.f, 0.f, 0.f, 0.f);
    float4 acc2 = make_float4(0.f, 0.f, 0.f, 0.f);
    while (j < end && (j & 3)) {
        int s0 = __ldg(&g_csr_src[j]);
        float w0 = ndd * __ldg(&g_dinv[s0]);
        float4 v0 = ((const float4*)(X + (size_t)s0 * HIDC))[lane];
        acc.x += w0 * v0.x; acc.y += w0 * v0.y; acc.z += w0 * v0.z; acc.w += w0 * v0.w;
        j++;
    }
    for (; j + 8 <= end; j += 8) {
        int4 ia = *(const int4*)&g_csr_src[j];
        int4 ib = *(const int4*)&g_csr_src[j + 4];
        float w0 = ndd * __ldg(&g_dinv[ia.x]), w1 = ndd * __ldg(&g_dinv[ia.y]);
        float w2 = ndd * __ldg(&g_dinv[ia.z]), w3 = ndd * __ldg(&g_dinv[ia.w]);
        float w4 = ndd * __ldg(&g_dinv[ib.x]), w5 = ndd * __ldg(&g_dinv[ib.y]);
        float w6 = ndd * __ldg(&g_dinv[ib.z]), w7 = ndd * __ldg(&g_dinv[ib.w]);
        float4 v0 = ((const float4*)(X + (size_t)ia.x * HIDC))[lane];
        float4 v1 = ((const float4*)(X + (size_t)ia.y * HIDC))[lane];
        float4 v2 = ((const float4*)(X + (size_t)ia.z * HIDC))[lane];
        float4 v3 = ((const float4*)(X + (size_t)ia.w * HIDC))[lane];
        float4 v4 = ((const float4*)(X + (size_t)ib.x * HIDC))[lane];
        float4 v5 = ((const float4*)(X + (size_t)ib.y * HIDC))[lane];
        float4 v6 = ((const float4*)(X + (size_t)ib.z * HIDC))[lane];
        float4 v7 = ((const float4*)(X + (size_t)ib.w * HIDC))[lane];
        acc.x  += w0 * v0.x + w1 * v1.x + w2 * v2.x + w3 * v3.x;
        acc.y  += w0 * v0.y + w1 * v1.y + w2 * v2.y + w3 * v3.y;
        acc.z  += w0 * v0.z + w1 * v1.z + w2 * v2.z + w3 * v3.z;
        acc.w  += w0 * v0.w + w1 * v1.w + w2 * v2.w + w3 * v3.w;
        acc2.x += w4 * v4.x + w5 * v5.x + w6 * v6.x + w7 * v7.x;
        acc2.y += w4 * v4.y + w5 * v5.y + w6 * v6.y + w7 * v7.y;
        acc2.z += w4 * v4.z + w5 * v5.z + w6 * v6.z + w7 * v7.z;
        acc2.w += w4 * v4.w + w5 * v5.w + w6 * v6.w + w7 * v7.w;
    }
    for (; j < end; j++) {
        int s0 = __ldg(&g_csr_src[j]);
        float w0 = ndd * __ldg(&g_dinv[s0]);
        float4 v0 = ((const float4*)(X + (size_t)s0 * HIDC))[lane];
        acc.x += w0 * v0.x; acc.y += w0 * v0.y; acc.z += w0 * v0.z; acc.w += w0 * v0.w;
    }
    acc.x += acc2.x; acc.y += acc2.y; acc.z += acc2.z; acc.w += acc2.w;
    size_t o = (size_t)d * HIDC + lane * 4;
    split_store4(acc, g_t1hi + o, g_t1lo + o);
    float4 xv = ((const float4*)(X + (size_t)d * HIDC))[lane];
    split_store4(xv, g_xhi + o, g_xlo + o);
}

// ---------------- gather 2: th -> split bf16 + own-row BN split ----------------
__global__ void __launch_bounds__(128, 12) k_gather2(const float* __restrict__ gamma,
                                                     const float* __restrict__ beta) {
    __shared__ float s_sc[128], s_sh[128];
    int t = threadIdx.x;
    {
        float mean = g_sum[t] * (1.0f / NN);
        float var = fmaxf(g_sumsq[t] * (1.0f / NN) - mean * mean, 0.f);
        float sc = gamma[t] * rsqrtf(var + EPSF);
        s_sc[t] = sc;
        s_sh[t] = beta[t] - mean * sc;
    }
    __syncthreads();

    int warp = (int)(((size_t)blockIdx.x * blockDim.x + t) >> 5);
    if (warp >= NN) return;
    int lane = t & 31;
    int d = warp;
    int j = g_rowptr[d], end = g_rowptr[d + 1];
    float ndd = -g_dinv[d];
    float4 sc = *(float4*)&s_sc[lane * 4];
    float4 sh = *(float4*)&s_sh[lane * 4];
    float4 acc = make_float4(0.f, 0.f, 0.f, 0.f);
    float4 acc2 = make_float4(0.f, 0.f, 0.f, 0.f);
#define BNR(v) \
    v.x = fmaxf(fmaf(v.x, sc.x, sh.x), 0.f); \
    v.y = fmaxf(fmaf(v.y, sc.y, sh.y), 0.f); \
    v.z = fmaxf(fmaf(v.z, sc.z, sh.z), 0.f); \
    v.w = fmaxf(fmaf(v.w, sc.w, sh.w), 0.f)
    while (j < end && (j & 3)) {
        int s0 = __ldg(&g_csr_src[j]);
        float w0 = ndd * __ldg(&g_dinv[s0]);
        float4 v0 = ((const float4*)(g_h + (size_t)s0 * HIDC))[lane];
        BNR(v0);
        acc.x += w0 * v0.x; acc.y += w0 * v0.y; acc.z += w0 * v0.z; acc.w += w0 * v0.w;
        j++;
    }
    for (; j + 8 <= end; j += 8) {
        int4 ia = *(const int4*)&g_csr_src[j];
        int4 ib = *(const int4*)&g_csr_src[j + 4];
        float w0 = ndd * __ldg(&g_dinv[ia.x]), w1 = ndd * __ldg(&g_dinv[ia.y]);
        float w2 = ndd * __ldg(&g_dinv[ia.z]), w3 = ndd * __ldg(&g_dinv[ia.w]);
        float w4 = ndd * __ldg(&g_dinv[ib.x]), w5 = ndd * __ldg(&g_dinv[ib.y]);
        float w6 = ndd * __ldg(&g_dinv[ib.z]), w7 = ndd * __ldg(&g_dinv[ib.w]);
        float4 v0 = ((const float4*)(g_h + (size_t)ia.x * HIDC))[lane];
        float4 v1 = ((const float4*)(g_h + (size_t)ia.y * HIDC))[lane];
        float4 v2 = ((const float4*)(g_h + (size_t)ia.z * HIDC))[lane];
        float4 v3 = ((const float4*)(g_h + (size_t)ia.w * HIDC))[lane];
        float4 v4 = ((const float4*)(g_h + (size_t)ib.x * HIDC))[lane];
        float4 v5 = ((const float4*)(g_h + (size_t)ib.y * HIDC))[lane];
        float4 v6 = ((const float4*)(g_h + (size_t)ib.z * HIDC))[lane];
        float4 v7 = ((const float4*)(g_h + (size_t)ib.w * HIDC))[lane];
        BNR(v0); BNR(v1); BNR(v2); BNR(v3); BNR(v4); BNR(v5); BNR(v6); BNR(v7);
        acc.x  += w0 * v0.x + w1 * v1.x + w2 * v2.x + w3 * v3.x;
        acc.y  += w0 * v0.y + w1 * v1.y + w2 * v2.y + w3 * v3.y;
        acc.z  += w0 * v0.z + w1 * v1.z + w2 * v2.z + w3 * v3.z;
        acc.w  += w0 * v0.w + w1 * v1.w + w2 * v2.w + w3 * v3.w;
        acc2.x += w4 * v4.x + w5 * v5.x + w6 * v6.x + w7 * v7.x;
        acc2.y += w4 * v4.y + w5 * v5.y + w6 * v6.y + w7 * v7.y;
        acc2.z += w4 * v4.z + w5 * v5.z + w6 * v6.z + w7 * v7.z;
        acc2.w += w4 * v4.w + w5 * v5.w + w6 * v6.w + w7 * v7.w;
    }
    for (; j < end; j++) {
        int s0 = __ldg(&g_csr_src[j]);
        float w0 = ndd * __ldg(&g_dinv[s0]);
        float4 v0 = ((const float4*)(g_h + (size_t)s0 * HIDC))[lane];
        BNR(v0);
        acc.x += w0 * v0.x; acc.y += w0 * v0.y; acc.z += w0 * v0.z; acc.w += w0 * v0.w;
    }
    acc.x += acc2.x; acc.y += acc2.y; acc.z += acc2.z; acc.w += acc2.w;
    size_t o = (size_t)d * HIDC + lane * 4;
    split_store4(acc, g_thhi + o, g_thlo + o);
    float4 hv = ((const float4*)(g_h + (size_t)d * HIDC))[lane];
    BNR(hv);
    split_store4(hv, g_hhi + o, g_hlo + o);
#undef BNR
}

// ---------------- HMMA split-bf16 GEMM, 2-stage pipelined cp.async, 8 K-chunks of 32 ----------------
#define CSTRIDE 80
#define CTILE (128 * CSTRIDE)
#define STG_B (4 * CTILE)
#define SOFF_AHI 0
#define SOFF_ALO CTILE
#define SOFF_BHI (2 * CTILE)
#define SOFF_BLO (3 * CTILE)
#define SMEM_TOT (2 * STG_B)

__global__ void __launch_bounds__(256, 2) k_tgemm(const float* __restrict__ biasExt,
                                                  float* __restrict__ outExt, int stage) {
    extern __shared__ char sm[];
    __shared__ float s_cs[128], s_cq[128];
    uint32_t sb = smem_u32(sm);
    int t = threadIdx.x;
    int row0 = blockIdx.x * 128;

    if (stage == 0 && t < 128) { s_cs[t] = 0.f; s_cq[t] = 0.f; }

    const __nv_bfloat16* A0hi = stage ? g_hhi : g_xhi;
    const __nv_bfloat16* A0lo = stage ? g_hlo : g_xlo;
    const __nv_bfloat16* A1hi = stage ? g_thhi : g_t1hi;
    const __nv_bfloat16* A1lo = stage ? g_thlo : g_t1lo;
    const __nv_bfloat16* Whi = stage ? g_w2hi : g_w1hi;
    const __nv_bfloat16* Wlo = stage ? g_w2lo : g_w1lo;
    const float* bias = stage ? g_bias2 : biasExt;

    int w = t >> 5, lane = t & 31;
    int warp_m = (w >> 1) * 32, warp_n = (w & 1) * 64;
    int gid = lane >> 2, tig = lane & 3;

    int arow = (lane & 7) + ((lane >> 3) & 1) * 8;
    uint32_t akb = (uint32_t)((lane >> 4) * 16);
    uint32_t aoff0 = (uint32_t)(warp_m + arow) * CSTRIDE + akb;
    uint32_t aoff1 = aoff0 + 16 * CSTRIDE;
    int brow = (lane & 7) + ((lane >> 4) & 1) * 8;
    uint32_t bkb = (uint32_t)(((lane >> 3) & 1) * 16);
    uint32_t boff = (uint32_t)(warp_n + brow) * CSTRIDE + bkb;

    float acc[2][8][4];
#pragma unroll
    for (int mt = 0; mt < 2; mt++)
#pragma unroll
        for (int j = 0; j < 8; j++)
#pragma unroll
            for (int q = 0; q < 4; q++) acc[mt][j][q] = 0.f;

    auto load_chunk = [&](int kc, int buf) {
        int colbase = (kc & 3) * 32;
        const __nv_bfloat16* cAhi = ((kc < 4) ? A0hi : A1hi) + colbase;
        const __nv_bfloat16* cAlo = ((kc < 4) ? A0lo : A1lo) + colbase;
        const __nv_bfloat16* cBhi = Whi + kc * 32;
        const __nv_bfloat16* cBlo = Wlo + kc * 32;
        uint32_t sbase = sb + buf * STG_B;
#pragma unroll
        for (int i = t; i < 2048; i += 256) {
            int tile = i >> 9, idx = i & 511;
            int row = idx >> 2, seg = idx & 3;
            uint32_t soff;
            const void* gp;
            int size = 16;
            if (tile == 0) {
                int gr = row0 + row;
                gp = cAhi + (size_t)gr * HIDC + seg * 8;
                soff = SOFF_AHI + row * CSTRIDE + seg * 16;
                if (gr >= NN) size = 0;
            } else if (tile == 1) {
                int gr = row0 + row;
                gp = cAlo + (size_t)gr * HIDC + seg * 8;
                soff = SOFF_ALO + row * CSTRIDE + seg * 16;
                if (gr >= NN) size = 0;
            } else if (tile == 2) {
                gp = cBhi + row * 256 + seg * 8;
                soff = SOFF_BHI + row * CSTRIDE + seg * 16;
            } else {
                gp = cBlo + row * 256 + seg * 8;
                soff = SOFF_BLO + row * CSTRIDE + seg * 16;
            }
            cpa16(sbase + soff, gp, size);
        }
        CP_COMMIT();
    };

    load_chunk(0, 0);
    for (int kc = 0; kc < 8; kc++) {
        int buf = kc & 1;
        if (kc < 7) {
            load_chunk(kc + 1, buf ^ 1);
            CP_WAIT1();
        } else {
            CP_WAIT0();
        }
        __syncthreads();

        uint32_t sbase = sb + buf * STG_B;
#pragma unroll
        for (int ks = 0; ks < 2; ks++) {
            uint32_t k2 = (uint32_t)ks * 32;
            uint32_t ah0[4], ah1[4], al0[4], al1[4];
            ldsm4(ah0, sbase + SOFF_AHI + aoff0 + k2);
            ldsm4(ah1, sbase + SOFF_AHI + aoff1 + k2);
            ldsm4(al0, sbase + SOFF_ALO + aoff0 + k2);
            ldsm4(al1, sbase + SOFF_ALO + aoff1 + k2);
#pragma unroll
            for (int np = 0; np < 4; np++) {
                uint32_t bh[4], bl[4];
                uint32_t bo = boff + (uint32_t)np * 16 * CSTRIDE + k2;
                ldsm4(bh, sbase + SOFF_BHI + bo);
                ldsm4(bl, sbase + SOFF_BLO + bo);
                mma_bf16(acc[0][2 * np],     ah0, bh);
                mma_bf16(acc[0][2 * np + 1], ah0, bh + 2);
                mma_bf16(acc[1][2 * np],     ah1, bh);
                mma_bf16(acc[1][2 * np + 1], ah1, bh + 2);
                mma_bf16(acc[0][2 * np],     al0, bh);
                mma_bf16(acc[0][2 * np + 1], al0, bh + 2);
                mma_bf16(acc[1][2 * np],     al1, bh);
                mma_bf16(acc[1][2 * np + 1], al1, bh + 2);
                mma_bf16(acc[0][2 * np],     ah0, bl);
                mma_bf16(acc[0][2 * np + 1], ah0, bl + 2);
                mma_bf16(acc[1][2 * np],     ah1, bl);
                mma_bf16(acc[1][2 * np + 1], ah1, bl + 2);
            }
        }
        __syncthreads();
    }

#pragma unroll
    for (int j = 0; j < 8; j++) {
        int n = warp_n + j * 8 + tig * 2;
        float b0 = bias[n], b1 = bias[n + 1];
#pragma unroll
        for (int mt = 0; mt < 2; mt++) {
            int r1 = row0 + warp_m + mt * 16 + gid;
            int r2 = r1 + 8;
            float2 v1 = make_float2(acc[mt][j][0] + b0, acc[mt][j][1] + b1);
            float2 v2 = make_float2(acc[mt][j][2] + b0, acc[mt][j][3] + b1);
            if (stage == 0) {
                if (r1 < NN) *(float2*)(g_h + (size_t)r1 * HIDC + n) = v1;
                if (r2 < NN) *(float2*)(g_h + (size_t)r2 * HIDC + n) = v2;
                float sx = (r1 < NN ? v1.x : 0.f) + (r2 < NN ? v2.x : 0.f);
                float sy = (r1 < NN ? v1.y : 0.f) + (r2 < NN ? v2.y : 0.f);
                float qx = (r1 < NN ? v1.x * v1.x : 0.f) + (r2 < NN ? v2.x * v2.x : 0.f);
                float qy = (r1 < NN ? v1.y * v1.y : 0.f) + (r2 < NN ? v2.y * v2.y : 0.f);
#pragma unroll
                for (int off = 4; off <= 16; off <<= 1) {
                    sx += __shfl_xor_sync(0xffffffffu, sx, off);
                    sy += __shfl_xor_sync(0xffffffffu, sy, off);
                    qx += __shfl_xor_sync(0xffffffffu, qx, off);
                    qy += __shfl_xor_sync(0xffffffffu, qy, off);
                }
                if (gid == 0) {
                    atomicAdd(&s_cs[n], sx);
                    atomicAdd(&s_cs[n + 1], sy);
                    atomicAdd(&s_cq[n], qx);
                    atomicAdd(&s_cq[n + 1], qy);
                }
            } else {
                int nl = (n < 64) ? n : (n - 64);
                size_t obase = (n < 64) ? 0 : (size_t)NN * OUTC;
                if (r1 < NN) *(float2*)(outExt + obase + (size_t)r1 * OUTC + nl) = v1;
                if (r2 < NN) *(float2*)(outExt + obase + (size_t)r2 * OUTC + nl) = v2;
            }
        }
    }

    if (stage == 0) {
        __syncthreads();
        if (t < 128) {
            atomicAdd(&g_sum[t], s_cs[t]);
            atomicAdd(&g_sumsq[t], s_cq[t]);
        }
    }
}

// ---------------- launch ----------------
extern "C" void kernel_launch(void* const* d_in, const int* in_sizes, int n_in,
                              void* d_out, int out_size) {
    const float* x     = (const float*)d_in[0];
    const int*   ei    = (const int*)d_in[1];
    const int*   src   = ei;
    const int*   dst   = ei + EE;
    const float* W1_0  = (const float*)d_in[2];
    const float* W1_1  = (const float*)d_in[3];
    const float* b1    = (const float*)d_in[4];
    const float* gamma = (const float*)d_in[5];
    const float* beta  = (const float*)d_in[6];
    const float* Wmu0  = (const float*)d_in[7];
    const float* Wmu1  = (const float*)d_in[8];
    const float* bmu   = (const float*)d_in[9];
    const float* Wls0  = (const float*)d_in[10];
    const float* Wls1  = (const float*)d_in[11];
    const float* bls   = (const float*)d_in[12];
    float* out = (float*)d_out;

    cudaFuncSetAttribute(k_tgemm, cudaFuncAttributeMaxDynamicSharedMemorySize, SMEM_TOT);

    k_prep<<<(EE + 255) / 256, 256>>>(src, dst, W1_0, W1_1, Wmu0, Wmu1, Wls0, Wls1, bmu, bls); // #1
    k_scan<<<NCHUNK, 256>>>();                                                 // #2
    k_fill<<<(EE + 255) / 256, 256>>>(src, dst);                               // #3
    k_gather1<<<(NN * 32 + 127) / 128, 128>>>(x);                              // #4
    k_tgemm<<<(NN + 127) / 128, 256, SMEM_TOT>>>(b1, nullptr, 0);              // #5
    k_gather2<<<(NN * 32 + 127) / 128, 128>>>(gamma, beta);                    // #6
    k_tgemm<<<(NN + 127) / 128, 256, SMEM_TOT>>>(nullptr, out, 1);             // #7
}